// round 14
// baseline (speedup 1.0000x reference)
#include <cuda_runtime.h>
#include <cuda_bf16.h>
#include <cstdint>

#define BB    2048
#define TT    256
#define HIDN  256
#define NG    1024          // 4*HIDN gate columns (permuted n' = 4j+gate)
#define KFEAT 128           // 70 real feature dims, zero-padded
#define NCHUNK 6            // 2 feat chunks + 4 hidden chunks, 64 bf16 each
#define BLKM  64            // batch rows per CTA (2 CTAs/SM)

// ---------------- device scratch (module-load allocated) -------------------
__device__ __align__(256) __nv_bfloat16 g_feat_hi[(size_t)BB * TT * KFEAT];
__device__ __align__(256) __nv_bfloat16 g_feat_lo[(size_t)BB * TT * KFEAT];
__device__ __align__(256) __nv_bfloat16 g_h_hi[2][(size_t)BB * HIDN];
__device__ __align__(256) __nv_bfloat16 g_h_lo[2][(size_t)BB * HIDN];
__device__ __align__(256) float         g_c[(size_t)BB * HIDN];
__device__ __align__(256) __nv_bfloat16 g_wih_hi[NG * KFEAT], g_wih_lo[NG * KFEAT];
__device__ __align__(256) __nv_bfloat16 g_whh_hi[NG * HIDN],  g_whh_lo[NG * HIDN];
__device__ __align__(256) float         g_bias[NG];

// ---------------- helpers (family-portable PTX only) -----------------------
__device__ __forceinline__ uint32_t smem_u32(const void* p) {
    uint32_t a;
    asm("{ .reg .u64 t; cvta.to.shared.u64 t, %1; cvt.u32.u64 %0, t; }" : "=r"(a) : "l"(p));
    return a;
}
#define CP_ASYNC16(dst, src) \
    asm volatile("cp.async.ca.shared.global [%0], [%1], 16;" :: "r"(dst), "l"(src) : "memory")
#define CP_COMMIT() asm volatile("cp.async.commit_group;" ::: "memory")
#define CP_WAIT(n)  asm volatile("cp.async.wait_group %0;" :: "n"(n) : "memory")

#define LDSM4(R, addr) \
    asm volatile("ldmatrix.sync.aligned.m8n8.x4.shared.b16 {%0,%1,%2,%3}, [%4];" \
        : "=r"((R)[0]), "=r"((R)[1]), "=r"((R)[2]), "=r"((R)[3]) : "r"(addr))
#define LDSM2(R, addr) \
    asm volatile("ldmatrix.sync.aligned.m8n8.x2.shared.b16 {%0,%1}, [%2];" \
        : "=r"((R)[0]), "=r"((R)[1]) : "r"(addr))

// m16n8k16 bf16 MMA, f32 accumulate (standard PTX, sm_80+, family-portable)
#define MMA16816(D, A, B) \
    asm volatile("mma.sync.aligned.m16n8k16.row.col.f32.bf16.bf16.f32 " \
        "{%0,%1,%2,%3}, {%4,%5,%6,%7}, {%8,%9}, {%0,%1,%2,%3};" \
        : "+f"((D)[0]), "+f"((D)[1]), "+f"((D)[2]), "+f"((D)[3]) \
        : "r"((A)[0]), "r"((A)[1]), "r"((A)[2]), "r"((A)[3]), \
          "r"((B)[0]), "r"((B)[1]))

__device__ __forceinline__ void split_bf16(float v, __nv_bfloat16& hi, __nv_bfloat16& lo) {
    hi = __float2bfloat16(v);
    lo = __float2bfloat16(v - __bfloat162float(hi));
}

// ---------------------------------------------------------------------------
// Featurize: conv(2x2,2->4) + ReLU + one-hot/reward/done -> bf16 hi/lo rows
// ---------------------------------------------------------------------------
__global__ void featurize_kernel(const float* __restrict__ x,
                                 const int*   __restrict__ prev_action,
                                 const float* __restrict__ prev_reward,
                                 const float* __restrict__ prev_done,
                                 const float* __restrict__ conv_w,
                                 const float* __restrict__ conv_b) {
    int g = blockIdx.x * blockDim.x + threadIdx.x;
    int t = g >> 11, b = g & (BB - 1);

    const float* xp = x + ((size_t)b * TT + t) * 50;
    float xv[50];
#pragma unroll
    for (int i = 0; i < 50; i++) xv[i] = xp[i];
    float cw[32];
#pragma unroll
    for (int i = 0; i < 32; i++) cw[i] = conv_w[i];
    float cb[4];
#pragma unroll
    for (int i = 0; i < 4; i++) cb[i] = conv_b[i];

    float v[70];
#pragma unroll
    for (int c = 0; c < 4; c++)
#pragma unroll
        for (int h = 0; h < 4; h++)
#pragma unroll
            for (int w = 0; w < 4; w++) {
                float s = cb[c];
#pragma unroll
                for (int i = 0; i < 2; i++)
#pragma unroll
                    for (int kh = 0; kh < 2; kh++)
#pragma unroll
                        for (int kw = 0; kw < 2; kw++)
                            s += xv[((h + kh) * 5 + (w + kw)) * 2 + i] *
                                 cw[((c * 2 + i) * 2 + kh) * 2 + kw];
                v[c * 16 + h * 4 + w] = fmaxf(s, 0.0f);
            }
    int a = prev_action[(size_t)b * TT + t];
#pragma unroll
    for (int k = 0; k < 4; k++) v[64 + k] = (a == k) ? 1.0f : 0.0f;
    v[68] = prev_reward[(size_t)b * TT + t];
    v[69] = prev_done[(size_t)b * TT + t];

    __nv_bfloat16* ph = g_feat_hi + (size_t)g * KFEAT;
    __nv_bfloat16* pl = g_feat_lo + (size_t)g * KFEAT;
#pragma unroll
    for (int k = 0; k < 70; k++) { __nv_bfloat16 h_, l_; split_bf16(v[k], h_, l_); ph[k] = h_; pl[k] = l_; }
#pragma unroll
    for (int k = 70; k < KFEAT; k++) { ph[k] = __float2bfloat16(0.f); pl[k] = __float2bfloat16(0.f); }
}

// ---------------------------------------------------------------------------
// One-time weight conversion: permuted rows n' = 4*j + gate (src n = gate*256+j)
// ---------------------------------------------------------------------------
__global__ void convert_weights_kernel(const float* __restrict__ w_ih,
                                       const float* __restrict__ w_hh,
                                       const float* __restrict__ b_ih,
                                       const float* __restrict__ b_hh) {
    int idx = blockIdx.x * blockDim.x + threadIdx.x;   // up to NG*HIDN
    {   // w_hh: [1024][256]
        int np = idx >> 8, k = idx & 255;
        int n = (np & 3) * HIDN + (np >> 2);
        __nv_bfloat16 h_, l_;
        split_bf16(w_hh[n * HIDN + k], h_, l_);
        g_whh_hi[np * HIDN + k] = h_;
        g_whh_lo[np * HIDN + k] = l_;
    }
    if (idx < NG * KFEAT) {   // w_ih padded 70 -> 128
        int np = idx >> 7, k = idx & 127;
        int n = (np & 3) * HIDN + (np >> 2);
        float v = (k < 70) ? w_ih[n * 70 + k] : 0.0f;
        __nv_bfloat16 h_, l_;
        split_bf16(v, h_, l_);
        g_wih_hi[np * KFEAT + k] = h_;
        g_wih_lo[np * KFEAT + k] = l_;
    }
    if (idx < NG) {
        int n = (idx & 3) * HIDN + (idx >> 2);
        g_bias[idx] = b_ih[n] + b_hh[n];
    }
}

// ---------------------------------------------------------------------------
// Init state: h -> bf16 hi/lo, c -> fp32, layout [b][j]
// ---------------------------------------------------------------------------
__global__ void init_state_kernel(const float* __restrict__ hidden) {
    int idx = blockIdx.x * blockDim.x + threadIdx.x;   // b*256 + j
    int b = idx >> 8, j = idx & 255;
    __nv_bfloat16 h_, l_;
    split_bf16(hidden[(size_t)b * 512 + j], h_, l_);
    g_h_hi[0][idx] = h_;
    g_h_lo[0][idx] = l_;
    g_c[idx] = hidden[(size_t)b * 512 + 256 + j];
}

// ---------------------------------------------------------------------------
// LSTM step: warp MMA (m16n8k16) + ldmatrix, 3-term hi/lo split, cp.async
// double-buffered. grid (32,8): 64 batch x 128 gate cols; 256 thr, 2 CTA/SM.
// ---------------------------------------------------------------------------
#define ROWP    72                        // padded row length (144 B)
#define TILEA_B (BLKM * ROWP * 2)         //  9216 B
#define TILEB_B (128 * ROWP * 2)          // 18432 B
#define STAGE_B (2 * TILEA_B + 2 * TILEB_B)   // 55296 B
#define SM_TOTAL (2 * STAGE_B)                // 110592 B

__device__ __forceinline__ void cpa_tile(uint32_t dst,
                                         const __nv_bfloat16* src, int stride,
                                         int rows, int tid) {
    int total = rows * 8;
    for (int idx = tid; idx < total; idx += 256) {
        int row = idx >> 3, c8 = idx & 7;
        CP_ASYNC16(dst + row * (ROWP * 2) + c8 * 16, src + (size_t)row * stride + c8 * 8);
    }
}

__global__ __launch_bounds__(256, 2)
void lstm_mma_step(float* __restrict__ out, int t, int pin) {
    extern __shared__ char smem[];
    uint32_t sb = smem_u32(smem);
    const int tid = threadIdx.x, wid = tid >> 5, lane = tid & 31;
    const int g = lane >> 2, tq = lane & 3;
    const int wm = wid & 1, wn = wid >> 1;      // 2 x 4 warp grid (32x32 tiles)
    const int m0 = blockIdx.x * BLKM;
    const int nt = blockIdx.y;                  // 128 n' = 32 j per CTA
    const int pout = pin ^ 1;

    float acc[2][4][4];
#pragma unroll
    for (int a = 0; a < 2; a++)
#pragma unroll
        for (int b = 0; b < 4; b++)
#pragma unroll
            for (int c = 0; c < 4; c++) acc[a][b][c] = 0.0f;

    const __nv_bfloat16* hhi = g_h_hi[pin];
    const __nv_bfloat16* hlo = g_h_lo[pin];

#define LOAD_STAGE(CK, BUF)                                                    \
    {                                                                          \
        uint32_t s0 = sb + (BUF) * STAGE_B;                                    \
        if ((CK) < 2) {                                                        \
            size_t ao = ((size_t)(t * BB + m0)) * KFEAT + (CK) * 64;           \
            size_t bo = ((size_t)(nt * 128)) * KFEAT + (CK) * 64;              \
            cpa_tile(s0,                        g_feat_hi + ao, KFEAT, BLKM, tid); \
            cpa_tile(s0 + TILEA_B,              g_feat_lo + ao, KFEAT, BLKM, tid); \
            cpa_tile(s0 + 2 * TILEA_B,          g_wih_hi  + bo, KFEAT, 128, tid);  \
            cpa_tile(s0 + 2 * TILEA_B + TILEB_B, g_wih_lo + bo, KFEAT, 128, tid);  \
        } else {                                                               \
            size_t ao = (size_t)m0 * HIDN + ((CK) - 2) * 64;                   \
            size_t bo = (size_t)(nt * 128) * HIDN + ((CK) - 2) * 64;           \
            cpa_tile(s0,                        hhi      + ao, HIDN, BLKM, tid);   \
            cpa_tile(s0 + TILEA_B,              hlo      + ao, HIDN, BLKM, tid);   \
            cpa_tile(s0 + 2 * TILEA_B,          g_whh_hi + bo, HIDN, 128, tid);    \
            cpa_tile(s0 + 2 * TILEA_B + TILEB_B, g_whh_lo + bo, HIDN, 128, tid);   \
        }                                                                      \
    }

    LOAD_STAGE(0, 0);
    CP_COMMIT();

    // ldmatrix lane address components (fixed per thread)
    const int aRow = (lane & 15);               // row within 16-row frag
    const int aKo  = (lane >> 4) * 16;          // +0 / +16 bytes (k half)
    const int bRow = (lane & 7);
    const int bKo  = ((lane >> 3) & 1) * 16;

#pragma unroll
    for (int ck = 0; ck < NCHUNK; ck++) {
        if (ck + 1 < NCHUNK) { LOAD_STAGE(ck + 1, (ck + 1) & 1); CP_COMMIT(); }
        if (ck + 1 < NCHUNK) CP_WAIT(1); else CP_WAIT(0);
        __syncthreads();

        uint32_t st = sb + (ck & 1) * STAGE_B;
        uint32_t aH = st, aL = st + TILEA_B;
        uint32_t bH = st + 2 * TILEA_B, bL = bH + TILEB_B;

#pragma unroll
        for (int ks = 0; ks < 4; ks++) {
            int kb = ks * 32;
            uint32_t ahi[2][4], alo[2][4], bhi[4][2], blo[4][2];
#pragma unroll
            for (int mi = 0; mi < 2; mi++) {
                uint32_t ro = (uint32_t)(wm * 32 + mi * 16 + aRow) * (ROWP * 2) + kb + aKo;
                LDSM4(ahi[mi], aH + ro);
                LDSM4(alo[mi], aL + ro);
            }
#pragma unroll
            for (int ni = 0; ni < 4; ni++) {
                uint32_t ro = (uint32_t)(wn * 32 + ni * 8 + bRow) * (ROWP * 2) + kb + bKo;
                LDSM2(bhi[ni], bH + ro);
                LDSM2(blo[ni], bL + ro);
            }
#pragma unroll
            for (int mi = 0; mi < 2; mi++)
#pragma unroll
                for (int ni = 0; ni < 4; ni++) {
                    MMA16816(acc[mi][ni], ahi[mi], bhi[ni]);
                    MMA16816(acc[mi][ni], ahi[mi], blo[ni]);
                    MMA16816(acc[mi][ni], alo[mi], bhi[ni]);
                }
        }
        __syncthreads();
    }
#undef LOAD_STAGE

    // ---- stage gates to SMEM (f32, padded 132-word rows; aliases stage 0)
    float (*sg)[132] = (float (*)[132])(smem);
#pragma unroll
    for (int mi = 0; mi < 2; mi++)
#pragma unroll
        for (int ni = 0; ni < 4; ni++) {
            int r0 = wm * 32 + mi * 16 + g;
            int c0 = wn * 32 + ni * 8 + 2 * tq;
            *(float2*)&sg[r0][c0]     = make_float2(acc[mi][ni][0], acc[mi][ni][1]);
            *(float2*)&sg[r0 + 8][c0] = make_float2(acc[mi][ni][2], acc[mi][ni][3]);
        }
    __syncthreads();

    // ---- fused LSTM pointwise update, fully coalesced global I/O
    __nv_bfloat16* ohi = g_h_hi[pout];
    __nv_bfloat16* olo = g_h_lo[pout];
#pragma unroll
    for (int i = 0; i < 8; i++) {
        int idx = i * 256 + tid;                // 2048 = 64 rows x 32 j
        int r = idx >> 5, jl = idx & 31;
        float4 gv = *(float4*)&sg[r][4 * jl];
        float4 bv = *(const float4*)(g_bias + 4 * (nt * 32 + jl));
        size_t ga = (size_t)(m0 + r) * HIDN + nt * 32 + jl;
        float cp = g_c[ga];
        float gi = gv.x + bv.x, gf = gv.y + bv.y;
        float gg = gv.z + bv.z, go = gv.w + bv.w;
        float si = 1.0f / (1.0f + __expf(-gi));
        float sf = 1.0f / (1.0f + __expf(-gf));
        float so = 1.0f / (1.0f + __expf(-go));
        float cn = sf * cp + si * tanhf(gg);
        float hn = so * tanhf(cn);
        g_c[ga] = cn;
        __nv_bfloat16 h_, l_;
        split_bf16(hn, h_, l_);
        ohi[ga] = h_;
        olo[ga] = l_;
        out[((size_t)(m0 + r) * TT + t) * HIDN + nt * 32 + jl] = hn;
    }
}

// ---------------------------------------------------------------------------
// hidden_out = concat(h_final, c); h_final read from features[:, T-1]
// ---------------------------------------------------------------------------
__global__ void write_hidden_kernel(const float* __restrict__ feat_out,
                                    float* __restrict__ out2) {
    int idx = blockIdx.x * blockDim.x + threadIdx.x;   // b*512 + col
    int b = idx >> 9, col = idx & 511;
    float v = (col < HIDN)
        ? feat_out[((size_t)b * TT + (TT - 1)) * HIDN + col]
        : g_c[(size_t)b * HIDN + (col - HIDN)];
    out2[idx] = v;
}

// ---------------------------------------------------------------------------
extern "C" void kernel_launch(void* const* d_in, const int* in_sizes, int n_in,
                              void* d_out, int out_size) {
    const float* x           = (const float*)d_in[0];
    const float* hidden      = (const float*)d_in[1];
    const int*   prev_action = (const int*)  d_in[2];
    const float* prev_reward = (const float*)d_in[3];
    const float* prev_done   = (const float*)d_in[4];
    const float* conv_w      = (const float*)d_in[5];
    const float* conv_b      = (const float*)d_in[6];
    const float* w_ih        = (const float*)d_in[7];
    const float* w_hh        = (const float*)d_in[8];
    const float* b_ih        = (const float*)d_in[9];
    const float* b_hh        = (const float*)d_in[10];
    float* out = (float*)d_out;

    cudaFuncSetAttribute(lstm_mma_step,
                         cudaFuncAttributeMaxDynamicSharedMemorySize, SM_TOTAL);

    featurize_kernel<<<(BB * TT) / 256, 256>>>(x, prev_action, prev_reward,
                                               prev_done, conv_w, conv_b);
    convert_weights_kernel<<<(NG * HIDN) / 256, 256>>>(w_ih, w_hh, b_ih, b_hh);
    init_state_kernel<<<(BB * HIDN) / 256, 256>>>(hidden);

    dim3 grid(BB / BLKM, NG / 128);
    for (int t = 0; t < TT; t++)
        lstm_mma_step<<<grid, 256, SM_TOTAL>>>(out, t, t & 1);

    write_hidden_kernel<<<(BB * 2 * HIDN) / 256, 256>>>(
        out, out + (size_t)BB * TT * HIDN);
}